// round 7
// baseline (speedup 1.0000x reference)
#include <cuda_runtime.h>
#include <cuda_bf16.h>

// Fused single-kernel deterministic reduction: out = sum(x) * a * b
// x: 8192*8192 fp32 (d_in[0]), a,b: scalar fp32 (d_in[1], d_in[2]).
//
// Mainloop = the best-measured variant (R2): grid-stride over float4,
// #pragma unroll 4, plain cached loads, 1184 x 256. 32-bit indexing
// (n4 = 2^24 fits comfortably in unsigned). launch_bounds(256,8) pins
// register allocation so 8 CTAs stay resident per SM.

#define R_BLOCKS  1184
#define R_THREADS 256

__device__ float g_partials[R_BLOCKS];
__device__ unsigned int g_count = 0;   // self-resetting: graph-replay safe

__device__ __forceinline__ float block_reduce(float s)
{
    #pragma unroll
    for (int o = 16; o > 0; o >>= 1)
        s += __shfl_xor_sync(0xffffffffu, s, o);

    __shared__ float sh[R_THREADS / 32];
    int lane = threadIdx.x & 31;
    int warp = threadIdx.x >> 5;
    if (lane == 0) sh[warp] = s;
    __syncthreads();

    if (warp == 0) {
        s = (lane < (R_THREADS / 32)) ? sh[lane] : 0.f;
        #pragma unroll
        for (int o = 16; o > 0; o >>= 1)
            s += __shfl_xor_sync(0xffffffffu, s, o);
    }
    return s;  // valid in warp 0 lane 0
}

__global__ void __launch_bounds__(R_THREADS, 8) reduce_fused(
    const float4* __restrict__ x4, unsigned n4,
    const float* __restrict__ a, const float* __restrict__ b,
    float* __restrict__ out)
{
    float s0 = 0.f, s1 = 0.f, s2 = 0.f, s3 = 0.f;
    unsigned idx    = blockIdx.x * R_THREADS + threadIdx.x;
    const unsigned stride = R_BLOCKS * R_THREADS;

    // Grid-stride loop, unroll 4: four independent LDG.128s per unrolled
    // body, short FADD chains via 4 accumulator lanes. This exact shape
    // measured fastest (R2 stage1, ~41us).
    #pragma unroll 4
    for (unsigned i = idx; i < n4; i += stride) {
        float4 v = x4[i];
        s0 += v.x; s1 += v.y; s2 += v.z; s3 += v.w;
    }
    float s = block_reduce((s0 + s1) + (s2 + s3));

    __shared__ bool is_last;
    if (threadIdx.x == 0) {
        g_partials[blockIdx.x] = s;
        __threadfence();
        unsigned int prev = atomicAdd(&g_count, 1u);
        is_last = (prev == (unsigned)gridDim.x - 1u);
    }
    __syncthreads();

    if (is_last) {
        // Deterministic final fold: fixed per-thread strided order.
        float t = 0.f;
        for (int i = threadIdx.x; i < R_BLOCKS; i += R_THREADS)
            t += g_partials[i];
        t = block_reduce(t);
        if (threadIdx.x == 0) {
            out[0] = t * a[0] * b[0];
            g_count = 0;   // reset for next graph replay
        }
    }
}

extern "C" void kernel_launch(void* const* d_in, const int* in_sizes, int n_in,
                              void* d_out, int out_size)
{
    const float4* x4 = (const float4*)d_in[0];
    const float* a   = (const float*)d_in[1];
    const float* b   = (const float*)d_in[2];
    float* out       = (float*)d_out;

    unsigned n4 = (unsigned)(in_sizes[0] >> 2);   // 8192*8192/4 = 2^24

    reduce_fused<<<R_BLOCKS, R_THREADS>>>(x4, n4, a, b, out);
}

// round 8
// speedup vs baseline: 1.1413x; 1.1413x over previous
#include <cuda_runtime.h>
#include <cuda_bf16.h>

// Fused single-kernel deterministic reduction: out = sum(x) * a * b
// x: 8192*8192 fp32 (d_in[0]), a,b: scalar fp32 (d_in[1], d_in[2]).
//
// Layout: block b owns contiguous chunk of 16384 float4 (256 KB).
//   thread t, group g loads p[0], p[256], p[512], p[768]
//   with p = x4 + b*16384 + g*1024 + t.
// -> one base register + 4KB immediate offsets per LDG.128, so ptxas emits
//    4 back-to-back independent loads per group (guaranteed MLP depth 4)
//    at ~28 registers (8 CTAs/SM). 1024 blocks * 16384 = 2^24 float4 exactly:
//    uniform trip count, zero bounds checks.

#define R_BLOCKS  1024
#define R_THREADS 256
#define R_GROUPS  16     // 16 groups * 4 loads = 64 float4 per thread

__device__ float g_partials[R_BLOCKS];
__device__ unsigned int g_count = 0;   // self-resetting: graph-replay safe

__device__ __forceinline__ float block_reduce(float s)
{
    #pragma unroll
    for (int o = 16; o > 0; o >>= 1)
        s += __shfl_xor_sync(0xffffffffu, s, o);

    __shared__ float sh[R_THREADS / 32];
    int lane = threadIdx.x & 31;
    int warp = threadIdx.x >> 5;
    if (lane == 0) sh[warp] = s;
    __syncthreads();

    if (warp == 0) {
        s = (lane < (R_THREADS / 32)) ? sh[lane] : 0.f;
        #pragma unroll
        for (int o = 16; o > 0; o >>= 1)
            s += __shfl_xor_sync(0xffffffffu, s, o);
    }
    return s;  // valid in warp 0 lane 0
}

__global__ void __launch_bounds__(R_THREADS) reduce_fused(
    const float4* __restrict__ x4,
    const float* __restrict__ a, const float* __restrict__ b,
    float* __restrict__ out)
{
    const float4* p = x4 + (unsigned)blockIdx.x * 16384u + threadIdx.x;

    float s0 = 0.f, s1 = 0.f, s2 = 0.f, s3 = 0.f;

    #pragma unroll 1
    for (int g = 0; g < R_GROUPS; g++) {
        // 4 independent LDG.128 off one base register (+0/+4KB/+8KB/+12KB),
        // all issued before any consumer -> 4-deep memory pipeline.
        float4 v0 = p[0];
        float4 v1 = p[256];
        float4 v2 = p[512];
        float4 v3 = p[768];
        s0 += (v0.x + v1.x) + (v2.x + v3.x);
        s1 += (v0.y + v1.y) + (v2.y + v3.y);
        s2 += (v0.z + v1.z) + (v2.z + v3.z);
        s3 += (v0.w + v1.w) + (v2.w + v3.w);
        p += 1024;
    }

    float s = block_reduce((s0 + s1) + (s2 + s3));

    __shared__ bool is_last;
    if (threadIdx.x == 0) {
        g_partials[blockIdx.x] = s;
        __threadfence();
        unsigned int prev = atomicAdd(&g_count, 1u);
        is_last = (prev == (unsigned)(R_BLOCKS - 1));
    }
    __syncthreads();

    if (is_last) {
        // Deterministic final fold: fixed per-thread strided order.
        float t = 0.f;
        #pragma unroll
        for (int i = 0; i < R_BLOCKS / R_THREADS; i++)
            t += g_partials[threadIdx.x + i * R_THREADS];
        t = block_reduce(t);
        if (threadIdx.x == 0) {
            out[0] = t * a[0] * b[0];
            g_count = 0;   // reset for next graph replay
        }
    }
}

extern "C" void kernel_launch(void* const* d_in, const int* in_sizes, int n_in,
                              void* d_out, int out_size)
{
    const float4* x4 = (const float4*)d_in[0];
    const float* a   = (const float*)d_in[1];
    const float* b   = (const float*)d_in[2];
    float* out       = (float*)d_out;

    reduce_fused<<<R_BLOCKS, R_THREADS>>>(x4, a, b, out);
}